// round 5
// baseline (speedup 1.0000x reference)
#include <cuda_runtime.h>
#include <cstdint>

#define M_DIM 16384
#define N_DIM 65536
#define NNZ   4194304
#define BATCH 16
#define HALF_NNZ (NNZ / 2)

// Scratch (allocation-free rule: __device__ globals). 16B-aligned for v4 ops.
__device__ __align__(16) float g_t1[M_DIM * BATCH];     // [M,16] -> then reused as r
__device__ __align__(16) float g_zuT[N_DIM * BATCH];    // [N,16]
__device__ __align__(16) float g_t2T[N_DIM * BATCH];    // [N,16]
__device__ float g_norm[BATCH];

__device__ __forceinline__ void red_add_v4(float* addr, float4 v) {
    asm volatile("red.global.add.v4.f32 [%0], {%1, %2, %3, %4};"
                 :: "l"(addr), "f"(v.x), "f"(v.y), "f"(v.z), "f"(v.w)
                 : "memory");
}

// K0: zu_T = (z*u) transposed to [N,16]; zero t1, t2T, norms
__global__ void k_init(const float* __restrict__ z, const float* __restrict__ u) {
    int idx = blockIdx.x * blockDim.x + threadIdx.x;   // idx = b*N + n (coalesced reads)
    if (idx < N_DIM * BATCH) {
        int b = idx >> 16;            // N = 65536
        int n = idx & (N_DIM - 1);
        g_zuT[n * BATCH + b] = z[idx] * u[idx];
        g_t2T[idx] = 0.0f;
        if (idx < M_DIM * BATCH) g_t1[idx] = 0.0f;
        if (idx < BATCH) g_norm[idx] = 0.0f;
    }
}

// Generic pipelined SpMM: out[sIdx[i], b4] += val[i] * in[gIdx[i], b4]
// 4 lanes per nnz; each thread handles nnz i and i+HALF_NNZ (2 gathers in flight).
template <bool DUMMY>
__global__ void __launch_bounds__(256) k_spmm(const float* __restrict__ vals,
                                              const int* __restrict__ gIdx,
                                              const int* __restrict__ sIdx,
                                              const float* __restrict__ src,
                                              float* __restrict__ dst) {
    int tid = blockIdx.x * blockDim.x + threadIdx.x;   // HALF_NNZ*4 threads
    int i  = tid >> 2;                                 // 0 .. HALF_NNZ-1
    int b4 = (tid & 3) << 2;
    if (i < HALF_NNZ) {
        int j = i + HALF_NNZ;
        float v0 = __ldg(&vals[i]);
        float v1 = __ldg(&vals[j]);
        int   g0 = __ldg(&gIdx[i]);
        int   g1 = __ldg(&gIdx[j]);
        int   s0 = __ldg(&sIdx[i]);
        int   s1 = __ldg(&sIdx[j]);
        // issue both gathers before consuming either (MLP=2 per thread)
        float4 x0 = *reinterpret_cast<const float4*>(&src[g0 * BATCH + b4]);
        float4 x1 = *reinterpret_cast<const float4*>(&src[g1 * BATCH + b4]);
        float4 p0 = make_float4(v0 * x0.x, v0 * x0.y, v0 * x0.z, v0 * x0.w);
        float4 p1 = make_float4(v1 * x1.x, v1 * x1.y, v1 * x1.z, v1 * x1.w);
        red_add_v4(&dst[s0 * BATCH + b4], p0);
        red_add_v4(&dst[s1 * BATCH + b4], p1);
    }
}

// K2: r = y - t1 (in place, [M,16] layout)
__global__ void k_residual(const float* __restrict__ y) {
    int idx = blockIdx.x * blockDim.x + threadIdx.x;   // idx = b*M + m (coalesced y read)
    if (idx < M_DIM * BATCH) {
        int b = idx >> 14;            // M = 16384
        int m = idx & (M_DIM - 1);
        int t = m * BATCH + b;
        g_t1[t] = y[idx] - g_t1[t];
    }
}

// K4: per-batch sum of squares of v = u * t2
__global__ void k_norm(const float* __restrict__ u) {
    int b = blockIdx.y;
    float acc = 0.0f;
    for (int n = blockIdx.x * blockDim.x + threadIdx.x; n < N_DIM;
         n += gridDim.x * blockDim.x) {
        float v = u[b * N_DIM + n] * g_t2T[n * BATCH + b];
        acc += v * v;
    }
    #pragma unroll
    for (int off = 16; off > 0; off >>= 1)
        acc += __shfl_down_sync(0xFFFFFFFFu, acc, off);
    __shared__ float warp_sums[8];
    int lane = threadIdx.x & 31, wid = threadIdx.x >> 5;
    if (lane == 0) warp_sums[wid] = acc;
    __syncthreads();
    if (wid == 0) {
        acc = (lane < (blockDim.x >> 5)) ? warp_sums[lane] : 0.0f;
        #pragma unroll
        for (int off = 4; off > 0; off >>= 1)
            acc += __shfl_down_sync(0xFFFFFFFFu, acc, off);
        if (lane == 0) atomicAdd(&g_norm[b], acc);
    }
}

// K5: out = z - eta * v / max(1, ||v||)
__global__ void k_final(const float* __restrict__ z,
                        const float* __restrict__ u,
                        const float* __restrict__ eta,
                        float* __restrict__ out) {
    int idx = blockIdx.x * blockDim.x + threadIdx.x;   // b*N + n
    if (idx < N_DIM * BATCH) {
        int b = idx >> 16;
        int n = idx & (N_DIM - 1);
        float nrm = sqrtf(g_norm[b]);
        float scale = 1.0f / fmaxf(1.0f, nrm);
        float v = u[idx] * g_t2T[n * BATCH + b];
        out[idx] = z[idx] - eta[0] * v * scale;
    }
}

extern "C" void kernel_launch(void* const* d_in, const int* in_sizes, int n_in,
                              void* d_out, int out_size) {
    const float* z      = (const float*)d_in[0];
    const float* u      = (const float*)d_in[1];
    const float* y      = (const float*)d_in[2];
    const float* A_vals = (const float*)d_in[3];
    const int*   A_rows = (const int*)d_in[4];
    const int*   A_cols = (const int*)d_in[5];
    const float* eta    = (const float*)d_in[6];
    float* out = (float*)d_out;

    float* t1  = nullptr, *zuT = nullptr, *t2T = nullptr;
    cudaGetSymbolAddress((void**)&t1,  g_t1);
    cudaGetSymbolAddress((void**)&zuT, g_zuT);
    cudaGetSymbolAddress((void**)&t2T, g_t2T);

    const int T = 256;
    k_init<<<(N_DIM * BATCH + T - 1) / T, T>>>(z, u);
    // spmm1: t1[row] += val * zuT[col]
    k_spmm<true><<<(HALF_NNZ * 4) / T, T>>>(A_vals, A_cols, A_rows, zuT, t1);
    k_residual<<<(M_DIM * BATCH + T - 1) / T, T>>>(y);
    // spmm2: t2T[col] += val * r[row]   (r lives in t1)
    k_spmm<false><<<(HALF_NNZ * 4) / T, T>>>(A_vals, A_rows, A_cols, t1, t2T);
    dim3 ng(64, BATCH, 1);
    k_norm<<<ng, T>>>(u);
    k_final<<<(N_DIM * BATCH + T - 1) / T, T>>>(z, u, eta, out);
}

// round 7
// speedup vs baseline: 1.1464x; 1.1464x over previous
#include <cuda_runtime.h>
#include <cuda_fp16.h>
#include <cstdint>

#define M_DIM 16384
#define N_DIM 65536
#define NNZ   4194304
#define BATCH 16

// fp16 scratch (allocation-free rule: __device__ globals). 32B rows.
__device__ __align__(32) __half g_zuT[N_DIM * BATCH];   // [N,16] half
__device__ __align__(32) __half g_t1h[M_DIM * BATCH];   // [M,16] half accumulator -> r
__device__ __align__(32) __half g_t2T[N_DIM * BATCH];   // [N,16] half accumulator
__device__ float g_norm[BATCH];

__device__ __forceinline__ void red_add_v4_f16x2(__half* addr,
                                                 __half2 a, __half2 b,
                                                 __half2 c, __half2 d) {
    uint32_t ua = *reinterpret_cast<uint32_t*>(&a);
    uint32_t ub = *reinterpret_cast<uint32_t*>(&b);
    uint32_t uc = *reinterpret_cast<uint32_t*>(&c);
    uint32_t ud = *reinterpret_cast<uint32_t*>(&d);
    asm volatile("red.global.add.noftz.v4.f16x2 [%0], {%1, %2, %3, %4};"
                 :: "l"(addr), "r"(ua), "r"(ub), "r"(uc), "r"(ud)
                 : "memory");
}

// K0: one thread per n. zuT[n,:] = half(z*u); zero t2T row; zero t1h row (n<M); norms.
__global__ void k_init(const float* __restrict__ z, const float* __restrict__ u) {
    int n = blockIdx.x * blockDim.x + threadIdx.x;
    if (n < N_DIM) {
        __half row[BATCH];
        #pragma unroll
        for (int b = 0; b < BATCH; b++)
            row[b] = __float2half(z[b * N_DIM + n] * u[b * N_DIM + n]);
        uint4* dst = reinterpret_cast<uint4*>(&g_zuT[n * BATCH]);
        dst[0] = reinterpret_cast<uint4*>(row)[0];
        dst[1] = reinterpret_cast<uint4*>(row)[1];
        uint4 zero = make_uint4(0, 0, 0, 0);
        uint4* t2 = reinterpret_cast<uint4*>(&g_t2T[n * BATCH]);
        t2[0] = zero; t2[1] = zero;
        if (n < M_DIM) {
            uint4* t1 = reinterpret_cast<uint4*>(&g_t1h[n * BATCH]);
            t1[0] = zero; t1[1] = zero;
        }
        if (n < BATCH) g_norm[n] = 0.0f;
    }
}

// SpMM: dst[sIdx[i], :] += val[i] * src[gIdx[i], :]  (fp16, 2 lanes/nnz, 16B each)
__global__ void __launch_bounds__(256) k_spmm(const float* __restrict__ vals,
                                              const int* __restrict__ gIdx,
                                              const int* __restrict__ sIdx,
                                              const __half* __restrict__ src,
                                              __half* __restrict__ dst) {
    int tid = blockIdx.x * blockDim.x + threadIdx.x;   // NNZ*2 threads
    int i  = tid >> 1;
    int h8 = (tid & 1) << 3;                           // half-element offset 0 or 8
    if (i < NNZ) {
        float v = __ldg(&vals[i]);
        int   g = __ldg(&gIdx[i]);
        int   s = __ldg(&sIdx[i]);
        uint4 x = *reinterpret_cast<const uint4*>(&src[g * BATCH + h8]);
        __half2 vv = __float2half2_rn(v);
        __half2 p0 = __hmul2(*reinterpret_cast<__half2*>(&x.x), vv);
        __half2 p1 = __hmul2(*reinterpret_cast<__half2*>(&x.y), vv);
        __half2 p2 = __hmul2(*reinterpret_cast<__half2*>(&x.z), vv);
        __half2 p3 = __hmul2(*reinterpret_cast<__half2*>(&x.w), vv);
        red_add_v4_f16x2(&dst[s * BATCH + h8], p0, p1, p2, p3);
    }
}

// K2: r[m,:] = y - t1 (one thread per m, fp32 math, store half)
__global__ void k_residual(const float* __restrict__ y) {
    int m = blockIdx.x * blockDim.x + threadIdx.x;
    if (m < M_DIM) {
        __half* rowp = &g_t1h[m * BATCH];
        __half row[BATCH];
        reinterpret_cast<uint4*>(row)[0] = reinterpret_cast<uint4*>(rowp)[0];
        reinterpret_cast<uint4*>(row)[1] = reinterpret_cast<uint4*>(rowp)[1];
        #pragma unroll
        for (int b = 0; b < BATCH; b++)
            row[b] = __float2half(y[b * M_DIM + m] - __half2float(row[b]));
        reinterpret_cast<uint4*>(rowp)[0] = reinterpret_cast<uint4*>(row)[0];
        reinterpret_cast<uint4*>(rowp)[1] = reinterpret_cast<uint4*>(row)[1];
    }
}

// K4: per-batch sumsq of v = u * t2. One thread per n (grid-stride), 16 local accs.
__global__ void k_norm(const float* __restrict__ u) {
    float acc[BATCH];
    #pragma unroll
    for (int b = 0; b < BATCH; b++) acc[b] = 0.0f;
    for (int n = blockIdx.x * blockDim.x + threadIdx.x; n < N_DIM;
         n += gridDim.x * blockDim.x) {
        __half row[BATCH];
        const __half* rowp = &g_t2T[n * BATCH];
        reinterpret_cast<uint4*>(row)[0] = reinterpret_cast<const uint4*>(rowp)[0];
        reinterpret_cast<uint4*>(row)[1] = reinterpret_cast<const uint4*>(rowp)[1];
        #pragma unroll
        for (int b = 0; b < BATCH; b++) {
            float v = u[b * N_DIM + n] * __half2float(row[b]);
            acc[b] += v * v;
        }
    }
    int lane = threadIdx.x & 31;
    #pragma unroll
    for (int b = 0; b < BATCH; b++) {
        float a = acc[b];
        #pragma unroll
        for (int off = 16; off > 0; off >>= 1)
            a += __shfl_down_sync(0xFFFFFFFFu, a, off);
        if (lane == 0) atomicAdd(&g_norm[b], a);
    }
}

// K5: out[b,n] = z - eta * v / max(1, ||v||). One thread per n.
__global__ void k_final(const float* __restrict__ z,
                        const float* __restrict__ u,
                        const float* __restrict__ eta,
                        float* __restrict__ out) {
    int n = blockIdx.x * blockDim.x + threadIdx.x;
    if (n < N_DIM) {
        __half row[BATCH];
        const __half* rowp = &g_t2T[n * BATCH];
        reinterpret_cast<uint4*>(row)[0] = reinterpret_cast<const uint4*>(rowp)[0];
        reinterpret_cast<uint4*>(row)[1] = reinterpret_cast<const uint4*>(rowp)[1];
        float e = eta[0];
        #pragma unroll
        for (int b = 0; b < BATCH; b++) {
            float scale = 1.0f / fmaxf(1.0f, sqrtf(g_norm[b]));
            float v = u[b * N_DIM + n] * __half2float(row[b]);
            out[b * N_DIM + n] = z[b * N_DIM + n] - e * v * scale;
        }
    }
}

extern "C" void kernel_launch(void* const* d_in, const int* in_sizes, int n_in,
                              void* d_out, int out_size) {
    const float* z      = (const float*)d_in[0];
    const float* u      = (const float*)d_in[1];
    const float* y      = (const float*)d_in[2];
    const float* A_vals = (const float*)d_in[3];
    const int*   A_rows = (const int*)d_in[4];
    const int*   A_cols = (const int*)d_in[5];
    const float* eta    = (const float*)d_in[6];
    float* out = (float*)d_out;

    __half* t1h = nullptr, *zuT = nullptr, *t2T = nullptr;
    cudaGetSymbolAddress((void**)&t1h, g_t1h);
    cudaGetSymbolAddress((void**)&zuT, g_zuT);
    cudaGetSymbolAddress((void**)&t2T, g_t2T);

    const int T = 256;
    k_init<<<N_DIM / T, T>>>(z, u);
    // spmm1: t1[row] += val * zuT[col]
    k_spmm<<<(NNZ * 2) / T, T>>>(A_vals, A_cols, A_rows, zuT, t1h);
    k_residual<<<M_DIM / T, T>>>(y);
    // spmm2: t2T[col] += val * r[row]  (r lives in t1h)
    k_spmm<<<(NNZ * 2) / T, T>>>(A_vals, A_rows, A_cols, t1h, t2T);
    k_norm<<<128, T>>>(u);
    k_final<<<N_DIM / T, T>>>(z, u, eta, out);
}

// round 11
// speedup vs baseline: 1.1820x; 1.0311x over previous
#include <cuda_runtime.h>
#include <cuda_fp16.h>
#include <cstdint>

#define M_DIM 16384
#define N_DIM 65536
#define NNZ   4194304
#define BATCH 16

// fp16 scratch (allocation-free rule: __device__ globals). 32B rows.
__device__ __align__(32) __half g_zuT[N_DIM * BATCH];   // [N,16] half
__device__ __align__(32) __half g_t1h[M_DIM * BATCH];   // [M,16] half accumulator -> r
__device__ __align__(32) __half g_t2T[N_DIM * BATCH];   // [N,16] half accumulator
__device__ float g_norm[BATCH];

__device__ __forceinline__ void red_add_v4_f16x2(__half* addr,
                                                 uint32_t a, uint32_t b,
                                                 uint32_t c, uint32_t d) {
    asm volatile("red.global.add.noftz.v4.f16x2 [%0], {%1, %2, %3, %4};"
                 :: "l"(addr), "r"(a), "r"(b), "r"(c), "r"(d)
                 : "memory");
}

// K0: thread per 4 consecutive n. zuT rows = half(z*u); zero t2T/t1h rows; norms.
__global__ void __launch_bounds__(256) k_init(const float* __restrict__ z,
                                              const float* __restrict__ u) {
    int t  = blockIdx.x * blockDim.x + threadIdx.x;   // N/4 = 16384 threads
    int n4 = t << 2;
    if (n4 < N_DIM) {
        __half row[4 * BATCH];                         // [q][b] packed q-major
        #pragma unroll
        for (int b = 0; b < BATCH; b++) {
            float4 zv = *reinterpret_cast<const float4*>(&z[b * N_DIM + n4]);
            float4 uv = *reinterpret_cast<const float4*>(&u[b * N_DIM + n4]);
            row[0 * BATCH + b] = __float2half(zv.x * uv.x);
            row[1 * BATCH + b] = __float2half(zv.y * uv.y);
            row[2 * BATCH + b] = __float2half(zv.z * uv.z);
            row[3 * BATCH + b] = __float2half(zv.w * uv.w);
        }
        uint4* dst = reinterpret_cast<uint4*>(&g_zuT[n4 * BATCH]);  // 128B contiguous
        #pragma unroll
        for (int q = 0; q < 8; q++) dst[q] = reinterpret_cast<uint4*>(row)[q];

        uint4 zero = make_uint4(0, 0, 0, 0);
        uint4* t2 = reinterpret_cast<uint4*>(&g_t2T[n4 * BATCH]);
        #pragma unroll
        for (int q = 0; q < 8; q++) t2[q] = zero;
        if (n4 < M_DIM) {
            uint4* t1 = reinterpret_cast<uint4*>(&g_t1h[n4 * BATCH]);
            #pragma unroll
            for (int q = 0; q < 8; q++) t1[q] = zero;
        }
        if (t < BATCH) g_norm[t] = 0.0f;
    }
}

// SpMM: dst[sIdx[i], :] += val[i] * src[gIdx[i], :]
// Lane pair (2k,2k+1) handles nnz pair (2p,2p+1); each lane does one nnz's 2 halves?
// No: thread handles one nnz's 16B half-row; pair-vectorized index loads.
__global__ void __launch_bounds__(256) k_spmm(const float2* __restrict__ vals2,
                                              const int2* __restrict__ gIdx2,
                                              const int2* __restrict__ sIdx2,
                                              const __half* __restrict__ src,
                                              __half* __restrict__ dst) {
    int tid = blockIdx.x * blockDim.x + threadIdx.x;   // NNZ*2 threads
    int q   = tid >> 2;                                // nnz-pair id (0..NNZ/2)
    int sel = (tid >> 1) & 1;                          // which nnz of the pair
    int h8  = (tid & 1) << 3;                          // half-row offset 0 or 8
    // lanes 4k..4k+3 share one int2/float2 load (L1 broadcast)
    float2 vv = __ldg(&vals2[q]);
    int2   gg = __ldg(&gIdx2[q]);
    int2   ss = __ldg(&sIdx2[q]);
    float v = sel ? vv.y : vv.x;
    int   g = sel ? gg.y : gg.x;
    int   s = sel ? ss.y : ss.x;
    uint4 x = *reinterpret_cast<const uint4*>(&src[g * BATCH + h8]);
    __half2 vh = __float2half2_rn(v);
    uint32_t p0, p1, p2, p3;
    __half2 r0 = __hmul2(*reinterpret_cast<__half2*>(&x.x), vh);
    __half2 r1 = __hmul2(*reinterpret_cast<__half2*>(&x.y), vh);
    __half2 r2 = __hmul2(*reinterpret_cast<__half2*>(&x.z), vh);
    __half2 r3 = __hmul2(*reinterpret_cast<__half2*>(&x.w), vh);
    p0 = *reinterpret_cast<uint32_t*>(&r0);
    p1 = *reinterpret_cast<uint32_t*>(&r1);
    p2 = *reinterpret_cast<uint32_t*>(&r2);
    p3 = *reinterpret_cast<uint32_t*>(&r3);
    red_add_v4_f16x2(&dst[s * BATCH + h8], p0, p1, p2, p3);
}

// K2: r[m4..m4+3,:] = y - t1 (fp32 math, half storage), thread per 4 rows
__global__ void __launch_bounds__(256) k_residual(const float* __restrict__ y) {
    int t  = blockIdx.x * blockDim.x + threadIdx.x;   // M/4 = 4096 threads
    int m4 = t << 2;
    if (m4 < M_DIM) {
        __half row[4 * BATCH];
        uint4* rp = reinterpret_cast<uint4*>(&g_t1h[m4 * BATCH]);
        #pragma unroll
        for (int q = 0; q < 8; q++) reinterpret_cast<uint4*>(row)[q] = rp[q];
        #pragma unroll
        for (int b = 0; b < BATCH; b++) {
            float4 yv = *reinterpret_cast<const float4*>(&y[b * M_DIM + m4]);
            row[0 * BATCH + b] = __float2half(yv.x - __half2float(row[0 * BATCH + b]));
            row[1 * BATCH + b] = __float2half(yv.y - __half2float(row[1 * BATCH + b]));
            row[2 * BATCH + b] = __float2half(yv.z - __half2float(row[2 * BATCH + b]));
            row[3 * BATCH + b] = __float2half(yv.w - __half2float(row[3 * BATCH + b]));
        }
        #pragma unroll
        for (int q = 0; q < 8; q++) rp[q] = reinterpret_cast<uint4*>(row)[q];
    }
}

// K4: per-batch sumsq of v = u * t2. Exactly one n-quad per thread, no loop.
__global__ void __launch_bounds__(256) k_norm(const float* __restrict__ u) {
    int t  = blockIdx.x * blockDim.x + threadIdx.x;   // 16384 threads (64 blocks)
    int n4 = t << 2;
    float acc[BATCH];
    __half row[4 * BATCH];
    const uint4* rp = reinterpret_cast<const uint4*>(&g_t2T[n4 * BATCH]);
    #pragma unroll
    for (int q = 0; q < 8; q++) reinterpret_cast<uint4*>(row)[q] = rp[q];
    #pragma unroll
    for (int b = 0; b < BATCH; b++) {
        float4 uv = *reinterpret_cast<const float4*>(&u[b * N_DIM + n4]);
        float v0 = uv.x * __half2float(row[0 * BATCH + b]);
        float v1 = uv.y * __half2float(row[1 * BATCH + b]);
        float v2 = uv.z * __half2float(row[2 * BATCH + b]);
        float v3 = uv.w * __half2float(row[3 * BATCH + b]);
        acc[b] = v0 * v0 + v1 * v1 + v2 * v2 + v3 * v3;
    }
    int lane = threadIdx.x & 31;
    #pragma unroll
    for (int b = 0; b < BATCH; b++) {
        float a = acc[b];
        #pragma unroll
        for (int off = 16; off > 0; off >>= 1)
            a += __shfl_down_sync(0xFFFFFFFFu, a, off);
        if (lane == 0) atomicAdd(&g_norm[b], a);
    }
}

// K5: out = z - eta * v / max(1, ||v||). Thread per n-quad.
__global__ void __launch_bounds__(256) k_final(const float* __restrict__ z,
                                               const float* __restrict__ u,
                                               const float* __restrict__ eta,
                                               float* __restrict__ out) {
    int t  = blockIdx.x * blockDim.x + threadIdx.x;   // 16384 threads
    int n4 = t << 2;
    __half row[4 * BATCH];
    const uint4* rp = reinterpret_cast<const uint4*>(&g_t2T[n4 * BATCH]);
    #pragma unroll
    for (int q = 0; q < 8; q++) reinterpret_cast<uint4*>(row)[q] = rp[q];
    float e = eta[0];
    #pragma unroll
    for (int b = 0; b < BATCH; b++) {
        float scale = e / fmaxf(1.0f, sqrtf(g_norm[b]));
        float4 zv = *reinterpret_cast<const float4*>(&z[b * N_DIM + n4]);
        float4 uv = *reinterpret_cast<const float4*>(&u[b * N_DIM + n4]);
        float4 o;
        o.x = zv.x - scale * uv.x * __half2float(row[0 * BATCH + b]);
        o.y = zv.y - scale * uv.y * __half2float(row[1 * BATCH + b]);
        o.z = zv.z - scale * uv.z * __half2float(row[2 * BATCH + b]);
        o.w = zv.w - scale * uv.w * __half2float(row[3 * BATCH + b]);
        *reinterpret_cast<float4*>(&out[b * N_DIM + n4]) = o;
    }
}

extern "C" void kernel_launch(void* const* d_in, const int* in_sizes, int n_in,
                              void* d_out, int out_size) {
    const float* z      = (const float*)d_in[0];
    const float* u      = (const float*)d_in[1];
    const float* y      = (const float*)d_in[2];
    const float* A_vals = (const float*)d_in[3];
    const int*   A_rows = (const int*)d_in[4];
    const int*   A_cols = (const int*)d_in[5];
    const float* eta    = (const float*)d_in[6];
    float* out = (float*)d_out;

    __half* t1h = nullptr, *zuT = nullptr, *t2T = nullptr;
    cudaGetSymbolAddress((void**)&t1h, g_t1h);
    cudaGetSymbolAddress((void**)&zuT, g_zuT);
    cudaGetSymbolAddress((void**)&t2T, g_t2T);

    const int T = 256;
    k_init<<<(N_DIM / 4) / T, T>>>(z, u);
    // spmm1: t1[row] += val * zuT[col]
    k_spmm<<<(NNZ * 2) / T, T>>>((const float2*)A_vals, (const int2*)A_cols,
                                 (const int2*)A_rows, zuT, t1h);
    k_residual<<<(M_DIM / 4) / T, T>>>(y);
    // spmm2: t2T[col] += val * r[row]  (r lives in t1h)
    k_spmm<<<(NNZ * 2) / T, T>>>((const float2*)A_vals, (const int2*)A_rows,
                                 (const int2*)A_cols, t1h, t2T);
    k_norm<<<(N_DIM / 4) / T, T>>>(u);
    k_final<<<(N_DIM / 4) / T, T>>>(z, u, eta, out);
}

// round 13
// speedup vs baseline: 1.2690x; 1.0737x over previous
#include <cuda_runtime.h>
#include <cuda_fp16.h>
#include <cstdint>

#define M_DIM 16384
#define N_DIM 65536
#define NNZ   4194304
#define BATCH 16

// fp16 scratch (allocation-free rule: __device__ globals). 32B rows.
__device__ __align__(32) __half g_zuT[N_DIM * BATCH];   // [N,16] half
__device__ __align__(32) __half g_t1h[M_DIM * BATCH];   // [M,16] half accumulator -> r
__device__ __align__(32) __half g_t2T[N_DIM * BATCH];   // [N,16] half accumulator
__device__ float g_norm[BATCH];

__device__ __forceinline__ void red_add_v4_f16x2(__half* addr,
                                                 uint32_t a, uint32_t b,
                                                 uint32_t c, uint32_t d) {
    asm volatile("red.global.add.noftz.v4.f16x2 [%0], {%1, %2, %3, %4};"
                 :: "l"(addr), "r"(a), "r"(b), "r"(c), "r"(d)
                 : "memory");
}

// K0: one thread per n (256 blocks). zuT[n,:] = half(z*u); zero t2T/t1h rows; norms.
__global__ void __launch_bounds__(256) k_init(const float* __restrict__ z,
                                              const float* __restrict__ u) {
    int n = blockIdx.x * blockDim.x + threadIdx.x;   // 65536 threads
    __half row[BATCH];
    #pragma unroll
    for (int b = 0; b < BATCH; b++)
        row[b] = __float2half(z[b * N_DIM + n] * u[b * N_DIM + n]);
    uint4* dst = reinterpret_cast<uint4*>(&g_zuT[n * BATCH]);
    dst[0] = reinterpret_cast<uint4*>(row)[0];
    dst[1] = reinterpret_cast<uint4*>(row)[1];
    uint4 zero = make_uint4(0, 0, 0, 0);
    uint4* t2 = reinterpret_cast<uint4*>(&g_t2T[n * BATCH]);
    t2[0] = zero; t2[1] = zero;
    if (n < M_DIM) {
        uint4* t1 = reinterpret_cast<uint4*>(&g_t1h[n * BATCH]);
        t1[0] = zero; t1[1] = zero;
    }
    if (n < BATCH) g_norm[n] = 0.0f;
}

// SpMM: dst[sIdx[i], :] += val[i] * src[gIdx[i], :]
// 2 lanes per nnz (16B half-row each); 8 lanes share one int4/float4 index load.
__global__ void __launch_bounds__(256) k_spmm(const float4* __restrict__ vals4,
                                              const int4* __restrict__ gIdx4,
                                              const int4* __restrict__ sIdx4,
                                              const __half* __restrict__ src,
                                              __half* __restrict__ dst) {
    int tid = blockIdx.x * blockDim.x + threadIdx.x;   // NNZ*2 threads
    int q   = tid >> 3;                                // 4-nnz group id
    int sel = (tid >> 1) & 3;                          // which nnz of the group
    int h8  = (tid & 1) << 3;                          // half-row offset 0 or 8
    float4 vv = __ldg(&vals4[q]);
    int4   gg = __ldg(&gIdx4[q]);
    int4   ss = __ldg(&sIdx4[q]);
    float v = (sel == 0) ? vv.x : (sel == 1) ? vv.y : (sel == 2) ? vv.z : vv.w;
    int   g = (sel == 0) ? gg.x : (sel == 1) ? gg.y : (sel == 2) ? gg.z : gg.w;
    int   s = (sel == 0) ? ss.x : (sel == 1) ? ss.y : (sel == 2) ? ss.z : ss.w;
    uint4 x = *reinterpret_cast<const uint4*>(&src[g * BATCH + h8]);
    __half2 vh = __float2half2_rn(v);
    __half2 r0 = __hmul2(*reinterpret_cast<__half2*>(&x.x), vh);
    __half2 r1 = __hmul2(*reinterpret_cast<__half2*>(&x.y), vh);
    __half2 r2 = __hmul2(*reinterpret_cast<__half2*>(&x.z), vh);
    __half2 r3 = __hmul2(*reinterpret_cast<__half2*>(&x.w), vh);
    red_add_v4_f16x2(&dst[s * BATCH + h8],
                     *reinterpret_cast<uint32_t*>(&r0),
                     *reinterpret_cast<uint32_t*>(&r1),
                     *reinterpret_cast<uint32_t*>(&r2),
                     *reinterpret_cast<uint32_t*>(&r3));
}

// K2: r[m,:] = y - t1 (one thread per m, 64 blocks; fp32 math, half storage)
__global__ void __launch_bounds__(256) k_residual(const float* __restrict__ y) {
    int m = blockIdx.x * blockDim.x + threadIdx.x;   // 16384 threads
    __half row[BATCH];
    uint4* rp = reinterpret_cast<uint4*>(&g_t1h[m * BATCH]);
    reinterpret_cast<uint4*>(row)[0] = rp[0];
    reinterpret_cast<uint4*>(row)[1] = rp[1];
    #pragma unroll
    for (int b = 0; b < BATCH; b++)
        row[b] = __float2half(y[b * M_DIM + m] - __half2float(row[b]));
    rp[0] = reinterpret_cast<uint4*>(row)[0];
    rp[1] = reinterpret_cast<uint4*>(row)[1];
}

// K4: per-batch sumsq of v = u * t2. Thread per n (stride 2 iters, 128 blocks).
// Two-level reduction: warp shuffle -> smem -> one atomic per block per b.
__global__ void __launch_bounds__(256) k_norm(const float* __restrict__ u) {
    float acc[BATCH];
    #pragma unroll
    for (int b = 0; b < BATCH; b++) acc[b] = 0.0f;
    for (int n = blockIdx.x * blockDim.x + threadIdx.x; n < N_DIM;
         n += gridDim.x * blockDim.x) {
        __half row[BATCH];
        const uint4* rp = reinterpret_cast<const uint4*>(&g_t2T[n * BATCH]);
        reinterpret_cast<uint4*>(row)[0] = rp[0];
        reinterpret_cast<uint4*>(row)[1] = rp[1];
        #pragma unroll
        for (int b = 0; b < BATCH; b++) {
            float v = u[b * N_DIM + n] * __half2float(row[b]);
            acc[b] += v * v;
        }
    }
    int lane = threadIdx.x & 31, wid = threadIdx.x >> 5;
    __shared__ float ws[8 * BATCH];
    #pragma unroll
    for (int b = 0; b < BATCH; b++) {
        float a = acc[b];
        #pragma unroll
        for (int off = 16; off > 0; off >>= 1)
            a += __shfl_down_sync(0xFFFFFFFFu, a, off);
        if (lane == 0) ws[wid * BATCH + b] = a;
    }
    __syncthreads();
    if (threadIdx.x < BATCH) {
        float s = 0.0f;
        #pragma unroll
        for (int w = 0; w < 8; w++) s += ws[w * BATCH + threadIdx.x];
        atomicAdd(&g_norm[threadIdx.x], s);
    }
}

// K5: out = z - eta * v / max(1, ||v||). One thread per n (256 blocks).
__global__ void __launch_bounds__(256) k_final(const float* __restrict__ z,
                                               const float* __restrict__ u,
                                               const float* __restrict__ eta,
                                               float* __restrict__ out) {
    int n = blockIdx.x * blockDim.x + threadIdx.x;   // 65536 threads
    __half row[BATCH];
    const uint4* rp = reinterpret_cast<const uint4*>(&g_t2T[n * BATCH]);
    reinterpret_cast<uint4*>(row)[0] = rp[0];
    reinterpret_cast<uint4*>(row)[1] = rp[1];
    float e = eta[0];
    #pragma unroll
    for (int b = 0; b < BATCH; b++) {
        float scale = e / fmaxf(1.0f, sqrtf(g_norm[b]));
        float v = u[b * N_DIM + n] * __half2float(row[b]);
        out[b * N_DIM + n] = z[b * N_DIM + n] - scale * v;
    }
}

extern "C" void kernel_launch(void* const* d_in, const int* in_sizes, int n_in,
                              void* d_out, int out_size) {
    const float* z      = (const float*)d_in[0];
    const float* u      = (const float*)d_in[1];
    const float* y      = (const float*)d_in[2];
    const float* A_vals = (const float*)d_in[3];
    const int*   A_rows = (const int*)d_in[4];
    const int*   A_cols = (const int*)d_in[5];
    const float* eta    = (const float*)d_in[6];
    float* out = (float*)d_out;

    __half* t1h = nullptr, *zuT = nullptr, *t2T = nullptr;
    cudaGetSymbolAddress((void**)&t1h, g_t1h);
    cudaGetSymbolAddress((void**)&zuT, g_zuT);
    cudaGetSymbolAddress((void**)&t2T, g_t2T);

    const int T = 256;
    k_init<<<N_DIM / T, T>>>(z, u);
    // spmm1: t1[row] += val * zuT[col]
    k_spmm<<<(NNZ * 2) / T, T>>>((const float4*)A_vals, (const int4*)A_cols,
                                 (const int4*)A_rows, zuT, t1h);
    k_residual<<<M_DIM / T, T>>>(y);
    // spmm2: t2T[col] += val * r[row]  (r lives in t1h)
    k_spmm<<<(NNZ * 2) / T, T>>>((const float4*)A_vals, (const int4*)A_rows,
                                 (const int4*)A_cols, t1h, t2T);
    k_norm<<<128, T>>>(u);
    k_final<<<N_DIM / T, T>>>(z, u, eta, out);
}

// round 14
// speedup vs baseline: 1.3622x; 1.0734x over previous
#include <cuda_runtime.h>
#include <cuda_fp16.h>
#include <cstdint>

#define M_DIM 16384
#define N_DIM 65536
#define NNZ   4194304
#define BATCH 16

// fp16 scratch (allocation-free rule: __device__ globals). 32B rows.
__device__ __align__(32) __half g_zuT[N_DIM * BATCH];   // [N,16] half
__device__ __align__(32) __half g_t1h[M_DIM * BATCH];   // [M,16] half accumulator -> r
__device__ __align__(32) __half g_t2T[N_DIM * BATCH];   // [N,16] half accumulator
__device__ float g_norm[BATCH];

__device__ __forceinline__ void red_add_v4_f16x2(__half* addr,
                                                 uint32_t a, uint32_t b,
                                                 uint32_t c, uint32_t d) {
    asm volatile("red.global.add.noftz.v4.f16x2 [%0], {%1, %2, %3, %4};"
                 :: "l"(addr), "r"(a), "r"(b), "r"(c), "r"(d)
                 : "memory");
}

// K0: one thread per n (256 blocks). zuT[n,:] = half(z*u); zero t2T/t1h rows; norms.
__global__ void __launch_bounds__(256) k_init(const float* __restrict__ z,
                                              const float* __restrict__ u) {
    int n = blockIdx.x * blockDim.x + threadIdx.x;   // 65536 threads
    __half row[BATCH];
    #pragma unroll
    for (int b = 0; b < BATCH; b++)
        row[b] = __float2half(z[b * N_DIM + n] * u[b * N_DIM + n]);
    uint4* dst = reinterpret_cast<uint4*>(&g_zuT[n * BATCH]);
    dst[0] = reinterpret_cast<uint4*>(row)[0];
    dst[1] = reinterpret_cast<uint4*>(row)[1];
    uint4 zero = make_uint4(0, 0, 0, 0);
    uint4* t2 = reinterpret_cast<uint4*>(&g_t2T[n * BATCH]);
    t2[0] = zero; t2[1] = zero;
    if (n < M_DIM) {
        uint4* t1 = reinterpret_cast<uint4*>(&g_t1h[n * BATCH]);
        t1[0] = zero; t1[1] = zero;
    }
    if (n < BATCH) g_norm[n] = 0.0f;
}

// SpMM: dst[sIdx[i], :] += val[i] * src[gIdx[i], :]
// 2 lanes per nnz (16B half-row each); 4 lanes share one int2/float2 index load.
// (R11 configuration — measured fastest at 47.9us.)
__global__ void __launch_bounds__(256) k_spmm(const float2* __restrict__ vals2,
                                              const int2* __restrict__ gIdx2,
                                              const int2* __restrict__ sIdx2,
                                              const __half* __restrict__ src,
                                              __half* __restrict__ dst) {
    int tid = blockIdx.x * blockDim.x + threadIdx.x;   // NNZ*2 threads
    int q   = tid >> 2;                                // nnz-pair id
    int sel = (tid >> 1) & 1;                          // which nnz of the pair
    int h8  = (tid & 1) << 3;                          // half-row offset 0 or 8
    float2 vv = __ldg(&vals2[q]);
    int2   gg = __ldg(&gIdx2[q]);
    int2   ss = __ldg(&sIdx2[q]);
    float v = sel ? vv.y : vv.x;
    int   g = sel ? gg.y : gg.x;
    int   s = sel ? ss.y : ss.x;
    uint4 x = *reinterpret_cast<const uint4*>(&src[g * BATCH + h8]);
    __half2 vh = __float2half2_rn(v);
    __half2 r0 = __hmul2(*reinterpret_cast<__half2*>(&x.x), vh);
    __half2 r1 = __hmul2(*reinterpret_cast<__half2*>(&x.y), vh);
    __half2 r2 = __hmul2(*reinterpret_cast<__half2*>(&x.z), vh);
    __half2 r3 = __hmul2(*reinterpret_cast<__half2*>(&x.w), vh);
    red_add_v4_f16x2(&dst[s * BATCH + h8],
                     *reinterpret_cast<uint32_t*>(&r0),
                     *reinterpret_cast<uint32_t*>(&r1),
                     *reinterpret_cast<uint32_t*>(&r2),
                     *reinterpret_cast<uint32_t*>(&r3));
}

// K2: r[m,:] = y - t1 (one thread per m, 64 blocks; fp32 math, half storage)
__global__ void __launch_bounds__(256) k_residual(const float* __restrict__ y) {
    int m = blockIdx.x * blockDim.x + threadIdx.x;   // 16384 threads
    __half row[BATCH];
    uint4* rp = reinterpret_cast<uint4*>(&g_t1h[m * BATCH]);
    reinterpret_cast<uint4*>(row)[0] = rp[0];
    reinterpret_cast<uint4*>(row)[1] = rp[1];
    #pragma unroll
    for (int b = 0; b < BATCH; b++)
        row[b] = __float2half(y[b * M_DIM + m] - __half2float(row[b]));
    rp[0] = reinterpret_cast<uint4*>(row)[0];
    rp[1] = reinterpret_cast<uint4*>(row)[1];
}

// K4: per-batch sumsq of v = u * t2. Thread per n (stride 2 iters, 128 blocks).
// Two-level reduction: warp shuffle -> smem -> one atomic per block per b.
__global__ void __launch_bounds__(256) k_norm(const float* __restrict__ u) {
    float acc[BATCH];
    #pragma unroll
    for (int b = 0; b < BATCH; b++) acc[b] = 0.0f;
    for (int n = blockIdx.x * blockDim.x + threadIdx.x; n < N_DIM;
         n += gridDim.x * blockDim.x) {
        __half row[BATCH];
        const uint4* rp = reinterpret_cast<const uint4*>(&g_t2T[n * BATCH]);
        reinterpret_cast<uint4*>(row)[0] = rp[0];
        reinterpret_cast<uint4*>(row)[1] = rp[1];
        #pragma unroll
        for (int b = 0; b < BATCH; b++) {
            float v = u[b * N_DIM + n] * __half2float(row[b]);
            acc[b] += v * v;
        }
    }
    int lane = threadIdx.x & 31, wid = threadIdx.x >> 5;
    __shared__ float ws[8 * BATCH];
    #pragma unroll
    for (int b = 0; b < BATCH; b++) {
        float a = acc[b];
        #pragma unroll
        for (int off = 16; off > 0; off >>= 1)
            a += __shfl_down_sync(0xFFFFFFFFu, a, off);
        if (lane == 0) ws[wid * BATCH + b] = a;
    }
    __syncthreads();
    if (threadIdx.x < BATCH) {
        float s = 0.0f;
        #pragma unroll
        for (int w = 0; w < 8; w++) s += ws[w * BATCH + threadIdx.x];
        atomicAdd(&g_norm[threadIdx.x], s);
    }
}

// K5: out = z - eta * v / max(1, ||v||). One thread per n (256 blocks).
__global__ void __launch_bounds__(256) k_final(const float* __restrict__ z,
                                               const float* __restrict__ u,
                                               const float* __restrict__ eta,
                                               float* __restrict__ out) {
    int n = blockIdx.x * blockDim.x + threadIdx.x;   // 65536 threads
    __half row[BATCH];
    const uint4* rp = reinterpret_cast<const uint4*>(&g_t2T[n * BATCH]);
    reinterpret_cast<uint4*>(row)[0] = rp[0];
    reinterpret_cast<uint4*>(row)[1] = rp[1];
    float e = eta[0];
    #pragma unroll
    for (int b = 0; b < BATCH; b++) {
        float scale = e / fmaxf(1.0f, sqrtf(g_norm[b]));
        float v = u[b * N_DIM + n] * __half2float(row[b]);
        out[b * N_DIM + n] = z[b * N_DIM + n] - scale * v;
    }
}

extern "C" void kernel_launch(void* const* d_in, const int* in_sizes, int n_in,
                              void* d_out, int out_size) {
    const float* z      = (const float*)d_in[0];
    const float* u      = (const float*)d_in[1];
    const float* y      = (const float*)d_in[2];
    const float* A_vals = (const float*)d_in[3];
    const int*   A_rows = (const int*)d_in[4];
    const int*   A_cols = (const int*)d_in[5];
    const float* eta    = (const float*)d_in[6];
    float* out = (float*)d_out;

    __half* t1h = nullptr, *zuT = nullptr, *t2T = nullptr;
    cudaGetSymbolAddress((void**)&t1h, g_t1h);
    cudaGetSymbolAddress((void**)&zuT, g_zuT);
    cudaGetSymbolAddress((void**)&t2T, g_t2T);

    const int T = 256;
    k_init<<<N_DIM / T, T>>>(z, u);
    // spmm1: t1[row] += val * zuT[col]
    k_spmm<<<(NNZ * 2) / T, T>>>((const float2*)A_vals, (const int2*)A_cols,
                                 (const int2*)A_rows, zuT, t1h);
    k_residual<<<M_DIM / T, T>>>(y);
    // spmm2: t2T[col] += val * r[row]  (r lives in t1h)
    k_spmm<<<(NNZ * 2) / T, T>>>((const float2*)A_vals, (const int2*)A_rows,
                                 (const int2*)A_cols, t1h, t2T);
    k_norm<<<128, T>>>(u);
    k_final<<<N_DIM / T, T>>>(z, u, eta, out);
}

// round 16
// speedup vs baseline: 1.3675x; 1.0039x over previous
#include <cuda_runtime.h>
#include <cuda_fp16.h>
#include <cstdint>

#define M_DIM 16384
#define N_DIM 65536
#define NNZ   4194304
#define BATCH 16

// fp16 scratch (allocation-free rule: __device__ globals). 32B rows.
__device__ __align__(32) __half g_zuT[N_DIM * BATCH];   // [N,16] half: zu -> later vT
__device__ __align__(32) __half g_t1h[M_DIM * BATCH];   // [M,16] half accumulator -> r
__device__ __align__(32) __half g_t2T[N_DIM * BATCH];   // [N,16] half accumulator
__device__ float g_norm[BATCH];

__device__ __forceinline__ void red_add_v4_f16x2(__half* addr,
                                                 uint32_t a, uint32_t b,
                                                 uint32_t c, uint32_t d) {
    asm volatile("red.global.add.noftz.v4.f16x2 [%0], {%1, %2, %3, %4};"
                 :: "l"(addr), "r"(a), "r"(b), "r"(c), "r"(d)
                 : "memory");
}

// K0: one thread per n (256 blocks). zuT[n,:] = half(z*u); zero t2T/t1h rows; norms.
__global__ void __launch_bounds__(256) k_init(const float* __restrict__ z,
                                              const float* __restrict__ u) {
    int n = blockIdx.x * blockDim.x + threadIdx.x;   // 65536 threads
    __half row[BATCH];
    #pragma unroll
    for (int b = 0; b < BATCH; b++)
        row[b] = __float2half(z[b * N_DIM + n] * u[b * N_DIM + n]);
    uint4* dst = reinterpret_cast<uint4*>(&g_zuT[n * BATCH]);
    dst[0] = reinterpret_cast<uint4*>(row)[0];
    dst[1] = reinterpret_cast<uint4*>(row)[1];
    uint4 zero = make_uint4(0, 0, 0, 0);
    uint4* t2 = reinterpret_cast<uint4*>(&g_t2T[n * BATCH]);
    t2[0] = zero; t2[1] = zero;
    if (n < M_DIM) {
        uint4* t1 = reinterpret_cast<uint4*>(&g_t1h[n * BATCH]);
        t1[0] = zero; t1[1] = zero;
    }
    if (n < BATCH) g_norm[n] = 0.0f;
}

// SpMM: dst[sIdx[i], :] += val[i] * src[gIdx[i], :]
// 2 lanes per nnz (16B half-row each); 4 lanes share one int2/float2 index load.
__global__ void __launch_bounds__(256) k_spmm(const float2* __restrict__ vals2,
                                              const int2* __restrict__ gIdx2,
                                              const int2* __restrict__ sIdx2,
                                              const __half* __restrict__ src,
                                              __half* __restrict__ dst) {
    int tid = blockIdx.x * blockDim.x + threadIdx.x;   // NNZ*2 threads
    int q   = tid >> 2;                                // nnz-pair id
    int sel = (tid >> 1) & 1;                          // which nnz of the pair
    int h8  = (tid & 1) << 3;                          // half-row offset 0 or 8
    float2 vv = __ldg(&vals2[q]);
    int2   gg = __ldg(&gIdx2[q]);
    int2   ss = __ldg(&sIdx2[q]);
    float v = sel ? vv.y : vv.x;
    int   g = sel ? gg.y : gg.x;
    int   s = sel ? ss.y : ss.x;
    uint4 x = *reinterpret_cast<const uint4*>(&src[g * BATCH + h8]);
    __half2 vh = __float2half2_rn(v);
    __half2 r0 = __hmul2(*reinterpret_cast<__half2*>(&x.x), vh);
    __half2 r1 = __hmul2(*reinterpret_cast<__half2*>(&x.y), vh);
    __half2 r2 = __hmul2(*reinterpret_cast<__half2*>(&x.z), vh);
    __half2 r3 = __hmul2(*reinterpret_cast<__half2*>(&x.w), vh);
    red_add_v4_f16x2(&dst[s * BATCH + h8],
                     *reinterpret_cast<uint32_t*>(&r0),
                     *reinterpret_cast<uint32_t*>(&r1),
                     *reinterpret_cast<uint32_t*>(&r2),
                     *reinterpret_cast<uint32_t*>(&r3));
}

// K2: r[m,:] = y - t1 (one thread per m; fp32 math, half storage)
__global__ void __launch_bounds__(256) k_residual(const float* __restrict__ y) {
    int m = blockIdx.x * blockDim.x + threadIdx.x;   // 16384 threads
    __half row[BATCH];
    uint4* rp = reinterpret_cast<uint4*>(&g_t1h[m * BATCH]);
    reinterpret_cast<uint4*>(row)[0] = rp[0];
    reinterpret_cast<uint4*>(row)[1] = rp[1];
    #pragma unroll
    for (int b = 0; b < BATCH; b++)
        row[b] = __float2half(y[b * M_DIM + m] - __half2float(row[b]));
    rp[0] = reinterpret_cast<uint4*>(row)[0];
    rp[1] = reinterpret_cast<uint4*>(row)[1];
}

// K4: per-batch sumsq of v = u * t2; also materialize vT (half) into g_zuT
// (zu no longer needed). Thread per n, stride loop, 128 blocks.
__global__ void __launch_bounds__(256) k_norm(const float* __restrict__ u) {
    float acc[BATCH];
    #pragma unroll
    for (int b = 0; b < BATCH; b++) acc[b] = 0.0f;
    for (int n = blockIdx.x * blockDim.x + threadIdx.x; n < N_DIM;
         n += gridDim.x * blockDim.x) {
        __half row[BATCH];
        const uint4* rp = reinterpret_cast<const uint4*>(&g_t2T[n * BATCH]);
        reinterpret_cast<uint4*>(row)[0] = rp[0];
        reinterpret_cast<uint4*>(row)[1] = rp[1];
        __half vrow[BATCH];
        #pragma unroll
        for (int b = 0; b < BATCH; b++) {
            float v = u[b * N_DIM + n] * __half2float(row[b]);
            acc[b] += v * v;
            vrow[b] = __float2half(v);
        }
        uint4* vp = reinterpret_cast<uint4*>(&g_zuT[n * BATCH]);
        vp[0] = reinterpret_cast<uint4*>(vrow)[0];
        vp[1] = reinterpret_cast<uint4*>(vrow)[1];
    }
    int lane = threadIdx.x & 31, wid = threadIdx.x >> 5;
    __shared__ float ws[8 * BATCH];
    #pragma unroll
    for (int b = 0; b < BATCH; b++) {
        float a = acc[b];
        #pragma unroll
        for (int off = 16; off > 0; off >>= 1)
            a += __shfl_down_sync(0xFFFFFFFFu, a, off);
        if (lane == 0) ws[wid * BATCH + b] = a;
    }
    __syncthreads();
    if (threadIdx.x < BATCH) {
        float s = 0.0f;
        #pragma unroll
        for (int w = 0; w < 8; w++) s += ws[w * BATCH + threadIdx.x];
        atomicAdd(&g_norm[threadIdx.x], s);
    }
}

// K5: out = z - eta * v / max(1, ||v||). Reads vT from g_zuT (no u, no t2T).
__global__ void __launch_bounds__(256) k_final(const float* __restrict__ z,
                                               const float* __restrict__ eta,
                                               float* __restrict__ out) {
    int n = blockIdx.x * blockDim.x + threadIdx.x;   // 65536 threads
    __half row[BATCH];
    const uint4* rp = reinterpret_cast<const uint4*>(&g_zuT[n * BATCH]);
    reinterpret_cast<uint4*>(row)[0] = rp[0];
    reinterpret_cast<uint4*>(row)[1] = rp[1];
    float e = eta[0];
    #pragma unroll
    for (int b = 0; b < BATCH; b++) {
        float scale = e / fmaxf(1.0f, sqrtf(g_norm[b]));
        out[b * N_DIM + n] = z[b * N_DIM + n] - scale * __half2float(row[b]);
    }
}

extern "C" void kernel_launch(void* const* d_in, const int* in_sizes, int n_in,
                              void* d_out, int out_size) {
    const float* z      = (const float*)d_in[0];
    const float* u      = (const float*)d_in[1];
    const float* y      = (const float*)d_in[2];
    const float* A_vals = (const float*)d_in[3];
    const int*   A_rows = (const int*)d_in[4];
    const int*   A_cols = (const int*)d_in[5];
    const float* eta    = (const float*)d_in[6];
    float* out = (float*)d_out;

    __half* t1h = nullptr, *zuT = nullptr, *t2T = nullptr;
    cudaGetSymbolAddress((void**)&t1h, g_t1h);
    cudaGetSymbolAddress((void**)&zuT, g_zuT);
    cudaGetSymbolAddress((void**)&t2T, g_t2T);

    // Maximize L1D for the gather-heavy spmm (smem unused there). Idempotent.
    static bool carveout_set = false;
    if (!carveout_set) {
        cudaFuncSetAttribute(k_spmm, cudaFuncAttributePreferredSharedMemoryCarveout, 0);
        carveout_set = true;
    }

    const int T = 256;
    k_init<<<N_DIM / T, T>>>(z, u);
    // spmm1: t1[row] += val * zuT[col]
    k_spmm<<<(NNZ * 2) / T, T>>>((const float2*)A_vals, (const int2*)A_cols,
                                 (const int2*)A_rows, zuT, t1h);
    k_residual<<<M_DIM / T, T>>>(y);
    // spmm2: t2T[col] += val * r[row]  (r lives in t1h)
    k_spmm<<<(NNZ * 2) / T, T>>>((const float2*)A_vals, (const int2*)A_rows,
                                 (const int2*)A_cols, t1h, t2T);
    k_norm<<<128, T>>>(u);
    k_final<<<N_DIM / T, T>>>(z, eta, out);
}

// round 17
// speedup vs baseline: 1.4198x; 1.0382x over previous
#include <cuda_runtime.h>
#include <cuda_fp16.h>
#include <cstdint>

#define M_DIM 16384
#define N_DIM 65536
#define NNZ   4194304
#define BATCH 16

// fp16 scratch (allocation-free rule: __device__ globals). 32B rows.
__device__ __align__(32) __half g_zuT[N_DIM * BATCH];   // [N,16] half
__device__ __align__(32) __half g_t1h[M_DIM * BATCH];   // [M,16] half accumulator -> r
__device__ __align__(32) __half g_t2T[N_DIM * BATCH];   // [N,16] half accumulator
__device__ float g_norm[BATCH];
__device__ unsigned int g_count;

__device__ __forceinline__ void red_add_v4_f16x2(__half* addr,
                                                 uint32_t a, uint32_t b,
                                                 uint32_t c, uint32_t d) {
    asm volatile("red.global.add.noftz.v4.f16x2 [%0], {%1, %2, %3, %4};"
                 :: "l"(addr), "r"(a), "r"(b), "r"(c), "r"(d)
                 : "memory");
}

// K0: one thread per n (256 blocks). zuT[n,:] = half(z*u); zero t2T/t1h rows;
// zero norms and the grid-barrier counter (deterministic per replay).
__global__ void __launch_bounds__(256) k_init(const float* __restrict__ z,
                                              const float* __restrict__ u) {
    int n = blockIdx.x * blockDim.x + threadIdx.x;   // 65536 threads
    __half row[BATCH];
    #pragma unroll
    for (int b = 0; b < BATCH; b++)
        row[b] = __float2half(z[b * N_DIM + n] * u[b * N_DIM + n]);
    uint4* dst = reinterpret_cast<uint4*>(&g_zuT[n * BATCH]);
    dst[0] = reinterpret_cast<uint4*>(row)[0];
    dst[1] = reinterpret_cast<uint4*>(row)[1];
    uint4 zero = make_uint4(0, 0, 0, 0);
    uint4* t2 = reinterpret_cast<uint4*>(&g_t2T[n * BATCH]);
    t2[0] = zero; t2[1] = zero;
    if (n < M_DIM) {
        uint4* t1 = reinterpret_cast<uint4*>(&g_t1h[n * BATCH]);
        t1[0] = zero; t1[1] = zero;
    }
    if (n < BATCH) g_norm[n] = 0.0f;
    if (n == 0) g_count = 0u;
}

// SpMM: dst[sIdx[i], :] += val[i] * src[gIdx[i], :]
// 2 lanes per nnz (16B half-row each); 4 lanes share one int2/float2 index load.
__global__ void __launch_bounds__(256) k_spmm(const float2* __restrict__ vals2,
                                              const int2* __restrict__ gIdx2,
                                              const int2* __restrict__ sIdx2,
                                              const __half* __restrict__ src,
                                              __half* __restrict__ dst) {
    int tid = blockIdx.x * blockDim.x + threadIdx.x;   // NNZ*2 threads
    int q   = tid >> 2;                                // nnz-pair id
    int sel = (tid >> 1) & 1;                          // which nnz of the pair
    int h8  = (tid & 1) << 3;                          // half-row offset 0 or 8
    float2 vv = __ldg(&vals2[q]);
    int2   gg = __ldg(&gIdx2[q]);
    int2   ss = __ldg(&sIdx2[q]);
    float v = sel ? vv.y : vv.x;
    int   g = sel ? gg.y : gg.x;
    int   s = sel ? ss.y : ss.x;
    uint4 x = *reinterpret_cast<const uint4*>(&src[g * BATCH + h8]);
    __half2 vh = __float2half2_rn(v);
    __half2 r0 = __hmul2(*reinterpret_cast<__half2*>(&x.x), vh);
    __half2 r1 = __hmul2(*reinterpret_cast<__half2*>(&x.y), vh);
    __half2 r2 = __hmul2(*reinterpret_cast<__half2*>(&x.z), vh);
    __half2 r3 = __hmul2(*reinterpret_cast<__half2*>(&x.w), vh);
    red_add_v4_f16x2(&dst[s * BATCH + h8],
                     *reinterpret_cast<uint32_t*>(&r0),
                     *reinterpret_cast<uint32_t*>(&r1),
                     *reinterpret_cast<uint32_t*>(&r2),
                     *reinterpret_cast<uint32_t*>(&r3));
}

// K2: r[m,:] = y - t1 (one thread per m; fp32 math, half storage)
__global__ void __launch_bounds__(256) k_residual(const float* __restrict__ y) {
    int m = blockIdx.x * blockDim.x + threadIdx.x;   // 16384 threads
    __half row[BATCH];
    uint4* rp = reinterpret_cast<uint4*>(&g_t1h[m * BATCH]);
    reinterpret_cast<uint4*>(row)[0] = rp[0];
    reinterpret_cast<uint4*>(row)[1] = rp[1];
    #pragma unroll
    for (int b = 0; b < BATCH; b++)
        row[b] = __float2half(y[b * M_DIM + m] - __half2float(row[b]));
    rp[0] = reinterpret_cast<uint4*>(row)[0];
    rp[1] = reinterpret_cast<uint4*>(row)[1];
}

// K-tail (fused norm+final): each thread owns one n; v kept in registers across
// a software grid barrier. 256 blocks x 256 threads = 65536 (all co-resident).
__global__ void __launch_bounds__(256) k_tail(const float* __restrict__ z,
                                              const float* __restrict__ u,
                                              const float* __restrict__ eta,
                                              float* __restrict__ out) {
    int n = blockIdx.x * blockDim.x + threadIdx.x;   // 65536 threads
    __half row[BATCH];
    const uint4* rp = reinterpret_cast<const uint4*>(&g_t2T[n * BATCH]);
    reinterpret_cast<uint4*>(row)[0] = rp[0];
    reinterpret_cast<uint4*>(row)[1] = rp[1];
    float v[BATCH];
    float acc[BATCH];
    #pragma unroll
    for (int b = 0; b < BATCH; b++) {
        v[b] = u[b * N_DIM + n] * __half2float(row[b]);
        acc[b] = v[b] * v[b];
    }
    // block reduction of acc -> one atomicAdd per b per block
    int lane = threadIdx.x & 31, wid = threadIdx.x >> 5;
    __shared__ float ws[8 * BATCH];
    #pragma unroll
    for (int b = 0; b < BATCH; b++) {
        float a = acc[b];
        #pragma unroll
        for (int off = 16; off > 0; off >>= 1)
            a += __shfl_down_sync(0xFFFFFFFFu, a, off);
        if (lane == 0) ws[wid * BATCH + b] = a;
    }
    __syncthreads();
    if (threadIdx.x < BATCH) {
        float s = 0.0f;
        #pragma unroll
        for (int w = 0; w < 8; w++) s += ws[w * BATCH + threadIdx.x];
        atomicAdd(&g_norm[threadIdx.x], s);
    }
    // grid barrier: make norm atomics visible, then arrive + spin
    __threadfence();
    __syncthreads();
    if (threadIdx.x == 0) {
        atomicAdd(&g_count, 1u);
        volatile unsigned int* cnt = &g_count;
        while (*cnt < gridDim.x) { }
    }
    __syncthreads();
    // read final norms via L2 (bypass possibly-stale L1), broadcast via smem
    __shared__ float scale_s[BATCH];
    if (threadIdx.x < BATCH) {
        float nrm;
        asm volatile("ld.global.cg.f32 %0, [%1];" : "=f"(nrm) : "l"(&g_norm[threadIdx.x]));
        scale_s[threadIdx.x] = eta[0] / fmaxf(1.0f, sqrtf(nrm));
    }
    __syncthreads();
    #pragma unroll
    for (int b = 0; b < BATCH; b++)
        out[b * N_DIM + n] = z[b * N_DIM + n] - scale_s[b] * v[b];
}

extern "C" void kernel_launch(void* const* d_in, const int* in_sizes, int n_in,
                              void* d_out, int out_size) {
    const float* z      = (const float*)d_in[0];
    const float* u      = (const float*)d_in[1];
    const float* y      = (const float*)d_in[2];
    const float* A_vals = (const float*)d_in[3];
    const int*   A_rows = (const int*)d_in[4];
    const int*   A_cols = (const int*)d_in[5];
    const float* eta    = (const float*)d_in[6];
    float* out = (float*)d_out;

    __half* t1h = nullptr, *zuT = nullptr, *t2T = nullptr;
    cudaGetSymbolAddress((void**)&t1h, g_t1h);
    cudaGetSymbolAddress((void**)&zuT, g_zuT);
    cudaGetSymbolAddress((void**)&t2T, g_t2T);

    // Maximize L1D for the gather-heavy spmm (smem unused there). Idempotent.
    static bool carveout_set = false;
    if (!carveout_set) {
        cudaFuncSetAttribute(k_spmm, cudaFuncAttributePreferredSharedMemoryCarveout, 0);
        carveout_set = true;
    }

    const int T = 256;
    k_init<<<N_DIM / T, T>>>(z, u);
    // spmm1: t1[row] += val * zuT[col]
    k_spmm<<<(NNZ * 2) / T, T>>>((const float2*)A_vals, (const int2*)A_cols,
                                 (const int2*)A_rows, zuT, t1h);
    k_residual<<<M_DIM / T, T>>>(y);
    // spmm2: t2T[col] += val * r[row]  (r lives in t1h)
    k_spmm<<<(NNZ * 2) / T, T>>>((const float2*)A_vals, (const int2*)A_rows,
                                 (const int2*)A_cols, t1h, t2T);
    k_tail<<<N_DIM / T, T>>>(z, u, eta, out);
}